// round 1
// baseline (speedup 1.0000x reference)
#include <cuda_runtime.h>
#include <cstdint>
#include <cstddef>

// Problem constants (fixed by the dataset)
#define NV    20000            // vertices per batch
#define NVT   80000            // B * N
#define KN    16               // neighbors
#define MM    9                // kernels
#define CC    64               // in channels
#define OO    64               // out channels

#define SST   584              // s_sm row stride (576 + 8) -> bank-conflict free
#define VTILE 64               // vertices per block
#define WCHUNK 96              // 576 = 6 * 96

// Device-global scratch (sanctioned workaround for no-alloc rule)
__device__ float g_uxc[NVT * 12];     // ux + c, padded to 12 floats/vertex
__device__ float g_vxp[NVT * 12];     // vx, padded to 12 floats/vertex
__device__ float g_wt[576 * 64];      // W transposed: Wt[m*64+c][o]

// ---- packed fp32x2 helpers (Blackwell; ptxas won't auto-fuse these) ----
__device__ __forceinline__ void fma2(unsigned long long& acc,
                                     unsigned long long a,
                                     unsigned long long b) {
    asm("fma.rn.f32x2 %0, %1, %2, %0;" : "+l"(acc) : "l"(a), "l"(b));
}
__device__ __forceinline__ unsigned long long pack2(float x, float y) {
    unsigned long long r;
    asm("mov.b64 %0, {%1, %2};" : "=l"(r) : "f"(x), "f"(y));
    return r;
}
__device__ __forceinline__ float2 unpack2(unsigned long long a) {
    float2 r;
    asm("mov.b64 {%0, %1}, %2;" : "=f"(r.x), "=f"(r.y) : "l"(a));
    return r;
}

// ---------------------------------------------------------------------------
// Kernel 1: transpose W [M,O,C] -> Wt [M*C, O]
// ---------------------------------------------------------------------------
__global__ void __launch_bounds__(256)
feast_wt(const float* __restrict__ W) {
    int tid = blockIdx.x * 256 + threadIdx.x;
    if (tid >= MM * OO * CC) return;
    int c = tid & 63;
    int o = (tid >> 6) & 63;
    int m = tid >> 12;
    g_wt[(m * 64 + c) * 64 + o] = W[tid];   // read coalesced over c
}

// ---------------------------------------------------------------------------
// Kernel 2: per-vertex projections  uxc[i,m] = x_i . u_m + c[m],  vx[i,m] = x_i . v_m
// One warp per vertex; 8 vertices per 256-thread block.
// ---------------------------------------------------------------------------
__global__ void __launch_bounds__(256)
feast_uvx(const float* __restrict__ x, const float* __restrict__ u,
          const float* __restrict__ v, const float* __restrict__ c) {
    const int wid  = threadIdx.x >> 5;
    const int lane = threadIdx.x & 31;
    const int gi   = blockIdx.x * 8 + wid;           // grid = NVT/8 exactly

    const float2 xx = *(const float2*)(x + (size_t)gi * CC + lane * 2);
    #pragma unroll
    for (int m = 0; m < MM; ++m) {
        const float2 uu = *(const float2*)(u + m * CC + lane * 2);
        const float2 vv = *(const float2*)(v + m * CC + lane * 2);
        float pu = xx.x * uu.x + xx.y * uu.y;
        float pv = xx.x * vv.x + xx.y * vv.y;
        #pragma unroll
        for (int off = 16; off > 0; off >>= 1) {
            pu += __shfl_xor_sync(0xffffffffu, pu, off);
            pv += __shfl_xor_sync(0xffffffffu, pv, off);
        }
        if (lane == 0) {
            g_uxc[gi * 12 + m] = pu + c[m];
            g_vxp[gi * 12 + m] = pv;
        }
    }
}

// ---------------------------------------------------------------------------
// Kernel 3: fused gather + softmax + s-accumulate + [64,576]x[576,64] GEMM
// ---------------------------------------------------------------------------
__global__ void __launch_bounds__(256, 1)
feast_main(const float* __restrict__ x, const int* __restrict__ adj,
           const float* __restrict__ bias, float* __restrict__ out) {
    extern __shared__ float sm[];
    float* s_sm  = sm;                         // VTILE * SST floats
    float* wt_sm = sm + VTILE * SST;           // WCHUNK * 64 floats
    float* q_sm  = wt_sm + WCHUNK * 64;        // 8 warps * 2 * 16 * 12 floats

    const int tid  = threadIdx.x;
    const int w    = tid >> 5;
    const int lane = tid & 31;
    const int kk   = lane & 15;                 // neighbor slot for stage A
    const int vp   = lane >> 4;                 // vertex-of-pair for stage A
    const int bv0  = blockIdx.x * VTILE;
    float* qbuf = q_sm + w * 384;

    // ======================= PHASE 1 =======================
    for (int it = 0; it < 4; ++it) {
        const int vpair = w * 8 + it * 2;

        // ---- stage A: lane (vp, kk) computes softmax over M for one neighbor ----
        const int giA  = bv0 + vpair + vp;
        const int base = (giA / NV) * NV;
        const int a    = adj[giA * KN + kk];
        const unsigned bal = __ballot_sync(0xffffffffu, a > 0);
        const int deg0 = __popc(bal & 0xffffu);
        const int deg1 = __popc(bal >> 16);
        const int j    = (a > 0) ? (base + a - 1) : -1;

        float q[9];
        if (a > 0) {
            const float4 uc0 = *(const float4*)(g_uxc + giA * 12);
            const float4 uc1 = *(const float4*)(g_uxc + giA * 12 + 4);
            const float4 uc2 = *(const float4*)(g_uxc + giA * 12 + 8);
            const float4 vv0 = *(const float4*)(g_vxp + j * 12);
            const float4 vv1 = *(const float4*)(g_vxp + j * 12 + 4);
            const float4 vv2 = *(const float4*)(g_vxp + j * 12 + 8);
            float l[9];
            l[0] = uc0.x + vv0.x; l[1] = uc0.y + vv0.y; l[2] = uc0.z + vv0.z; l[3] = uc0.w + vv0.w;
            l[4] = uc1.x + vv1.x; l[5] = uc1.y + vv1.y; l[6] = uc1.z + vv1.z; l[7] = uc1.w + vv1.w;
            l[8] = uc2.x + vv2.x;
            float mx = l[0];
            #pragma unroll
            for (int m = 1; m < 9; ++m) mx = fmaxf(mx, l[m]);
            float ssum = 0.f;
            #pragma unroll
            for (int m = 0; m < 9; ++m) { q[m] = __expf(l[m] - mx); ssum += q[m]; }
            float r;
            asm("rcp.approx.f32 %0, %1;" : "=f"(r) : "f"(ssum));
            #pragma unroll
            for (int m = 0; m < 9; ++m) q[m] *= r;
        } else {
            #pragma unroll
            for (int m = 0; m < 9; ++m) q[m] = 0.f;
        }
        float* qk = qbuf + (vp * 16 + kk) * 12;
        *(float4*)(qk)     = make_float4(q[0], q[1], q[2], q[3]);
        *(float4*)(qk + 4) = make_float4(q[4], q[5], q[6], q[7]);
        *(float4*)(qk + 8) = make_float4(q[8], __int_as_float(j), 0.f, 0.f);
        __syncwarp();

        // ---- stage B: lanes = channel pairs; accumulate s[m, 2lane..2lane+1] ----
        #pragma unroll
        for (int vsel = 0; vsel < 2; ++vsel) {
            const float* qb = qbuf + vsel * 192;
            float sxv[9], syv[9];
            #pragma unroll
            for (int m = 0; m < 9; ++m) { sxv[m] = 0.f; syv[m] = 0.f; }
            #pragma unroll 8
            for (int k2 = 0; k2 < KN; ++k2) {
                const float4 qa  = *(const float4*)(qb + k2 * 12);
                const float4 qb4 = *(const float4*)(qb + k2 * 12 + 4);
                const float4 qc  = *(const float4*)(qb + k2 * 12 + 8);
                const int j2 = __float_as_int(qc.y);
                if (j2 >= 0) {
                    const float2 xj = *(const float2*)(x + (size_t)j2 * CC + lane * 2);
                    sxv[0] += qa.x  * xj.x;  syv[0] += qa.x  * xj.y;
                    sxv[1] += qa.y  * xj.x;  syv[1] += qa.y  * xj.y;
                    sxv[2] += qa.z  * xj.x;  syv[2] += qa.z  * xj.y;
                    sxv[3] += qa.w  * xj.x;  syv[3] += qa.w  * xj.y;
                    sxv[4] += qb4.x * xj.x;  syv[4] += qb4.x * xj.y;
                    sxv[5] += qb4.y * xj.x;  syv[5] += qb4.y * xj.y;
                    sxv[6] += qb4.z * xj.x;  syv[6] += qb4.z * xj.y;
                    sxv[7] += qb4.w * xj.x;  syv[7] += qb4.w * xj.y;
                    sxv[8] += qc.x  * xj.x;  syv[8] += qc.x  * xj.y;
                }
            }
            const int dg = vsel ? deg1 : deg0;
            const float scl = (dg > 0) ? (1.0f / (float)dg) : 0.0f;
            float* srow = s_sm + (vpair + vsel) * SST + lane * 2;
            #pragma unroll
            for (int m = 0; m < 9; ++m)
                *(float2*)(srow + m * 64) = make_float2(sxv[m] * scl, syv[m] * scl);
        }
        __syncwarp();
    }
    __syncthreads();

    // ======================= PHASE 2: out = s @ Wt + b =======================
    const int tx = tid & 7;                    // 8 output columns per thread
    const int ty = tid >> 3;                   // vertex ty and ty+32
    const float* s1 = s_sm + ty * SST;
    const float* s2 = s_sm + (ty + 32) * SST;
    unsigned long long acc1[4] = {0ull, 0ull, 0ull, 0ull};
    unsigned long long acc2[4] = {0ull, 0ull, 0ull, 0ull};

    for (int ch = 0; ch < 6; ++ch) {
        // stage 24KB Wt chunk into smem (coalesced float4)
        const float4* gsrc = (const float4*)(g_wt + ch * (WCHUNK * 64));
        float4* gdst = (float4*)wt_sm;
        #pragma unroll
        for (int i = 0; i < (WCHUNK * 64 / 4) / 256; ++i)
            gdst[tid + i * 256] = gsrc[tid + i * 256];
        __syncthreads();

        const float* s1c = s1 + ch * WCHUNK;
        const float* s2c = s2 + ch * WCHUNK;
        #pragma unroll 8
        for (int kr = 0; kr < WCHUNK; ++kr) {
            const float a1 = s1c[kr];
            const float a2 = s2c[kr];
            const unsigned long long aa1 = pack2(a1, a1);
            const unsigned long long aa2 = pack2(a2, a2);
            const ulonglong2* bp = (const ulonglong2*)(wt_sm + kr * 64 + tx * 8);
            const ulonglong2 bA = bp[0];
            const ulonglong2 bB = bp[1];
            fma2(acc1[0], aa1, bA.x); fma2(acc1[1], aa1, bA.y);
            fma2(acc1[2], aa1, bB.x); fma2(acc1[3], aa1, bB.y);
            fma2(acc2[0], aa2, bA.x); fma2(acc2[1], aa2, bA.y);
            fma2(acc2[2], aa2, bB.x); fma2(acc2[3], aa2, bB.y);
        }
        __syncthreads();
    }

    const float4 bv_0 = *(const float4*)(bias + tx * 8);
    const float4 bv_1 = *(const float4*)(bias + tx * 8 + 4);
    {
        float2 r0 = unpack2(acc1[0]), r1 = unpack2(acc1[1]);
        float2 r2 = unpack2(acc1[2]), r3 = unpack2(acc1[3]);
        float* o1 = out + (size_t)(bv0 + ty) * OO + tx * 8;
        *(float4*)(o1)     = make_float4(r0.x + bv_0.x, r0.y + bv_0.y, r1.x + bv_0.z, r1.y + bv_0.w);
        *(float4*)(o1 + 4) = make_float4(r2.x + bv_1.x, r2.y + bv_1.y, r3.x + bv_1.z, r3.y + bv_1.w);
    }
    {
        float2 r0 = unpack2(acc2[0]), r1 = unpack2(acc2[1]);
        float2 r2 = unpack2(acc2[2]), r3 = unpack2(acc2[3]);
        float* o2 = out + (size_t)(bv0 + ty + 32) * OO + tx * 8;
        *(float4*)(o2)     = make_float4(r0.x + bv_0.x, r0.y + bv_0.y, r1.x + bv_0.z, r1.y + bv_0.w);
        *(float4*)(o2 + 4) = make_float4(r2.x + bv_1.x, r2.y + bv_1.y, r3.x + bv_1.z, r3.y + bv_1.w);
    }
}

// ---------------------------------------------------------------------------
// Host launcher (graph-capturable: kernel launches only)
// ---------------------------------------------------------------------------
extern "C" void kernel_launch(void* const* d_in, const int* in_sizes, int n_in,
                              void* d_out, int out_size) {
    const float* x   = (const float*)d_in[0];  // [B,N,C]
    const int*   adj = (const int*)  d_in[1];  // [B,N,K]
    const float* W   = (const float*)d_in[2];  // [M,O,C]
    const float* b   = (const float*)d_in[3];  // [O]
    const float* u   = (const float*)d_in[4];  // [M,C]
    const float* v   = (const float*)d_in[5];  // [M,C]
    const float* c   = (const float*)d_in[6];  // [M]
    float* out = (float*)d_out;

    feast_wt<<<(MM * OO * CC + 255) / 256, 256>>>(W);
    feast_uvx<<<NVT / 8, 256>>>(x, u, v, c);

    const size_t smem_bytes =
        (size_t)(VTILE * SST + WCHUNK * 64 + 8 * 384) * sizeof(float);  // 186368 B
    cudaFuncSetAttribute(feast_main, cudaFuncAttributeMaxDynamicSharedMemorySize,
                         (int)smem_bytes);
    feast_main<<<NVT / VTILE, 256, smem_bytes>>>(x, adj, b, out);
}

// round 2
// speedup vs baseline: 1.6496x; 1.6496x over previous
#include <cuda_runtime.h>
#include <cstdint>
#include <cstddef>

// Problem constants (fixed by the dataset)
#define NV    20000            // vertices per batch
#define NVT   80000            // B * N
#define KN    16               // neighbors
#define MM    9                // kernels
#define CC    64               // in channels
#define OO    64               // out channels

#define SST    580             // s_sm row stride (576 + 4), mod 32 == 4
#define VTILE  64              // vertices per block
#define WCHUNK 96              // K-rows per staged Wt chunk (288 = 3 * 96 per half)
#define NTHREADS 512

// Device-global scratch (sanctioned workaround for no-alloc rule)
__device__ float g_uxc[NVT * 12];     // ux + c, padded to 12 floats/vertex
__device__ float g_vxp[NVT * 12];     // vx, padded to 12 floats/vertex
__device__ float g_wt[576 * 64];      // W transposed: Wt[m*64+c][o]

// ---- packed fp32x2 helpers (Blackwell; ptxas won't auto-fuse these) ----
__device__ __forceinline__ void fma2(unsigned long long& acc,
                                     unsigned long long a,
                                     unsigned long long b) {
    asm("fma.rn.f32x2 %0, %1, %2, %0;" : "+l"(acc) : "l"(a), "l"(b));
}
__device__ __forceinline__ unsigned long long pack2(float x, float y) {
    unsigned long long r;
    asm("mov.b64 %0, {%1, %2};" : "=l"(r) : "f"(x), "f"(y));
    return r;
}
__device__ __forceinline__ float2 unpack2(unsigned long long a) {
    float2 r;
    asm("mov.b64 {%0, %1}, %2;" : "=f"(r.x), "=f"(r.y) : "l"(a));
    return r;
}

// ---------------------------------------------------------------------------
// Kernel 1: transpose W [M,O,C] -> Wt [M*C, O]
// ---------------------------------------------------------------------------
__global__ void __launch_bounds__(256)
feast_wt(const float* __restrict__ W) {
    int tid = blockIdx.x * 256 + threadIdx.x;
    if (tid >= MM * OO * CC) return;
    int c = tid & 63;
    int o = (tid >> 6) & 63;
    int m = tid >> 12;
    g_wt[(m * 64 + c) * 64 + o] = W[tid];   // read coalesced over c
}

// ---------------------------------------------------------------------------
// Kernel 2: per-vertex projections uxc[i,m] = x_i.u_m + c[m], vx[i,m] = x_i.v_m
// ---------------------------------------------------------------------------
__global__ void __launch_bounds__(256)
feast_uvx(const float* __restrict__ x, const float* __restrict__ u,
          const float* __restrict__ v, const float* __restrict__ c) {
    const int wid  = threadIdx.x >> 5;
    const int lane = threadIdx.x & 31;
    const int gi   = blockIdx.x * 8 + wid;           // grid = NVT/8 exactly

    const float2 xx = *(const float2*)(x + (size_t)gi * CC + lane * 2);
    #pragma unroll
    for (int m = 0; m < MM; ++m) {
        const float2 uu = *(const float2*)(u + m * CC + lane * 2);
        const float2 vv = *(const float2*)(v + m * CC + lane * 2);
        float pu = xx.x * uu.x + xx.y * uu.y;
        float pv = xx.x * vv.x + xx.y * vv.y;
        #pragma unroll
        for (int off = 16; off > 0; off >>= 1) {
            pu += __shfl_xor_sync(0xffffffffu, pu, off);
            pv += __shfl_xor_sync(0xffffffffu, pv, off);
        }
        if (lane == 0) {
            g_uxc[gi * 12 + m] = pu + c[m];
            g_vxp[gi * 12 + m] = pv;
        }
    }
}

// ---------------------------------------------------------------------------
// Kernel 3: fused gather + softmax + s-accumulate + [64,576]x[576,64] GEMM
// 512 threads. Phase 2 is split-K: half 0 handles K rows [0,288),
// half 1 handles [288,576) with its own Wt smem buffer; partials reduced.
// ---------------------------------------------------------------------------
__global__ void __launch_bounds__(NTHREADS, 1)
feast_main(const float* __restrict__ x, const int* __restrict__ adj,
           const float* __restrict__ bias, float* __restrict__ out) {
    extern __shared__ float sm[];
    float* s_sm  = sm;                         // VTILE * SST = 37120 floats
    float* wt_sm = sm + VTILE * SST;           // 2 * 96 * 64 = 12288 floats
    float* q_sm  = wt_sm + 2 * WCHUNK * 64;    // 6144 floats

    const int tid  = threadIdx.x;
    const int w    = tid >> 5;
    const int lane = tid & 31;
    const int kk   = lane & 15;                 // neighbor slot for stage A
    const int vp   = lane >> 4;                 // vertex-of-pair for stage A
    const int bv0  = blockIdx.x * VTILE;
    float* qbuf = q_sm + w * 384;

    // ======================= PHASE 1 =======================
    // 16 warps x 2 iterations x 2 vertices = 64 vertices
    #pragma unroll
    for (int it = 0; it < 2; ++it) {
        const int vpair = w * 4 + it * 2;

        // ---- stage A: lane (vp, kk) -> softmax over M for one neighbor ----
        const int giA  = bv0 + vpair + vp;
        const int base = (giA / NV) * NV;
        const int a    = adj[giA * KN + kk];
        const unsigned bal = __ballot_sync(0xffffffffu, a > 0);
        const int deg0 = __popc(bal & 0xffffu);
        const int deg1 = __popc(bal >> 16);
        const int j    = (a > 0) ? (base + a - 1) : -1;

        float q[9];
        if (a > 0) {
            const float4 uc0 = *(const float4*)(g_uxc + giA * 12);
            const float4 uc1 = *(const float4*)(g_uxc + giA * 12 + 4);
            const float4 uc2 = *(const float4*)(g_uxc + giA * 12 + 8);
            const float4 vv0 = *(const float4*)(g_vxp + j * 12);
            const float4 vv1 = *(const float4*)(g_vxp + j * 12 + 4);
            const float4 vv2 = *(const float4*)(g_vxp + j * 12 + 8);
            float l[9];
            l[0] = uc0.x + vv0.x; l[1] = uc0.y + vv0.y; l[2] = uc0.z + vv0.z; l[3] = uc0.w + vv0.w;
            l[4] = uc1.x + vv1.x; l[5] = uc1.y + vv1.y; l[6] = uc1.z + vv1.z; l[7] = uc1.w + vv1.w;
            l[8] = uc2.x + vv2.x;
            float mx = l[0];
            #pragma unroll
            for (int m = 1; m < 9; ++m) mx = fmaxf(mx, l[m]);
            float ssum = 0.f;
            #pragma unroll
            for (int m = 0; m < 9; ++m) { q[m] = __expf(l[m] - mx); ssum += q[m]; }
            float r;
            asm("rcp.approx.f32 %0, %1;" : "=f"(r) : "f"(ssum));
            #pragma unroll
            for (int m = 0; m < 9; ++m) q[m] *= r;
        } else {
            #pragma unroll
            for (int m = 0; m < 9; ++m) q[m] = 0.f;
        }
        float* qk = qbuf + (vp * 16 + kk) * 12;
        *(float4*)(qk)     = make_float4(q[0], q[1], q[2], q[3]);
        *(float4*)(qk + 4) = make_float4(q[4], q[5], q[6], q[7]);
        *(float4*)(qk + 8) = make_float4(q[8], __int_as_float(j), 0.f, 0.f);
        __syncwarp();

        // ---- stage B: lane <-> channels (lane, lane+32); m-paired fp32x2 accs ----
        #pragma unroll
        for (int vsel = 0; vsel < 2; ++vsel) {
            const float* qb = qbuf + vsel * 192;
            unsigned long long accA[4] = {0ull,0ull,0ull,0ull};   // ch lane,  m pairs 0-7
            unsigned long long accB[4] = {0ull,0ull,0ull,0ull};   // ch lane+32
            float acc8a = 0.f, acc8b = 0.f;                        // m = 8
            #pragma unroll 8
            for (int k2 = 0; k2 < KN; ++k2) {
                const ulonglong2 qp0 = *(const ulonglong2*)(qb + k2 * 12);      // (q0,q1),(q2,q3)
                const ulonglong2 qp1 = *(const ulonglong2*)(qb + k2 * 12 + 4);  // (q4,q5),(q6,q7)
                const float2     qt  = *(const float2*)(qb + k2 * 12 + 8);      // q8, j
                const int j2 = __float_as_int(qt.y);
                if (j2 >= 0) {
                    const float x0 = x[j2 * CC + lane];
                    const float x1 = x[j2 * CC + lane + 32];
                    const unsigned long long xx0 = pack2(x0, x0);
                    const unsigned long long xx1 = pack2(x1, x1);
                    fma2(accA[0], qp0.x, xx0); fma2(accA[1], qp0.y, xx0);
                    fma2(accA[2], qp1.x, xx0); fma2(accA[3], qp1.y, xx0);
                    fma2(accB[0], qp0.x, xx1); fma2(accB[1], qp0.y, xx1);
                    fma2(accB[2], qp1.x, xx1); fma2(accB[3], qp1.y, xx1);
                    acc8a += qt.x * x0;
                    acc8b += qt.x * x1;
                }
            }
            const int dg = vsel ? deg1 : deg0;
            const float scl = (dg > 0) ? (1.0f / (float)dg) : 0.0f;
            float* srow = s_sm + (vpair + vsel) * SST;
            #pragma unroll
            for (int mp = 0; mp < 4; ++mp) {
                const float2 a0 = unpack2(accA[mp]);
                const float2 b0 = unpack2(accB[mp]);
                srow[(2*mp)   * 64 + lane]      = a0.x * scl;
                srow[(2*mp+1) * 64 + lane]      = a0.y * scl;
                srow[(2*mp)   * 64 + lane + 32] = b0.x * scl;
                srow[(2*mp+1) * 64 + lane + 32] = b0.y * scl;
            }
            srow[8 * 64 + lane]      = acc8a * scl;
            srow[8 * 64 + lane + 32] = acc8b * scl;
        }
        __syncwarp();
    }

    // ======================= PHASE 2: out = s @ Wt + b (split-K) ===========
    const int half = tid >> 8;                 // 0 or 1
    const int t    = tid & 255;
    const int tx   = t & 7;                    // 8 output cols (o = tx*8 .. +7)
    const int ty   = t >> 3;                   // rows ty and ty+32
    float* mybuf = wt_sm + half * (WCHUNK * 64);
    const float* s0 = s_sm + ty * SST + half * 288;
    const float* s1 = s_sm + (ty + 32) * SST + half * 288;
    unsigned long long acc0[4] = {0ull,0ull,0ull,0ull};
    unsigned long long acc1[4] = {0ull,0ull,0ull,0ull};

    // prefetch my first chunk into registers (overlaps phase-1 tail)
    const int gchunk0 = half * 3;
    float4 pre[6];
    {
        const float4* src = (const float4*)(g_wt + gchunk0 * (WCHUNK * 64));
        #pragma unroll
        for (int i = 0; i < 6; ++i) pre[i] = src[t + i * 256];
    }

    for (int ch = 0; ch < 3; ++ch) {
        // store prefetched chunk with bank-conflict-free permutation:
        // row element o -> ((o>>2)&1)*32 + (o>>3)*4 + (o&3)
        #pragma unroll
        for (int i = 0; i < 6; ++i) {
            const int idx = t + i * 256;           // float4 index in chunk
            const int kr  = idx >> 4;
            const int jj  = idx & 15;              // covers o = 4*jj .. 4*jj+3
            const int dpos = kr * 16 + (jj & 1) * 8 + (jj >> 1);
            ((float4*)mybuf)[dpos] = pre[i];
        }
        __syncthreads();   // also orders s_sm (phase 1) before first compute

        if (ch < 2) {
            const float4* src = (const float4*)(g_wt + (gchunk0 + ch + 1) * (WCHUNK * 64));
            #pragma unroll
            for (int i = 0; i < 6; ++i) pre[i] = src[t + i * 256];
        }

        const float* sa = s0 + ch * WCHUNK;
        const float* sb = s1 + ch * WCHUNK;
        #pragma unroll 4
        for (int kr = 0; kr < WCHUNK; kr += 2) {
            const float2 a2 = *(const float2*)(sa + kr);
            const float2 b2 = *(const float2*)(sb + kr);
            #pragma unroll
            for (int q = 0; q < 2; ++q) {
                const float av = q ? a2.y : a2.x;
                const float bv = q ? b2.y : b2.x;
                const unsigned long long pa = pack2(av, av);
                const unsigned long long pb = pack2(bv, bv);
                const float* row = mybuf + (kr + q) * 64;
                const ulonglong2 wA = *(const ulonglong2*)(row + tx * 4);       // o: 8tx..+3
                const ulonglong2 wB = *(const ulonglong2*)(row + 32 + tx * 4);  // o: 8tx+4..+7
                fma2(acc0[0], pa, wA.x); fma2(acc0[1], pa, wA.y);
                fma2(acc0[2], pa, wB.x); fma2(acc0[3], pa, wB.y);
                fma2(acc1[0], pb, wA.x); fma2(acc1[1], pb, wA.y);
                fma2(acc1[2], pb, wB.x); fma2(acc1[3], pb, wB.y);
            }
        }
        __syncthreads();   // before overwriting mybuf
    }

    // ---- reduce the two K-halves ----
    float* red = q_sm + t * 20;
    if (half == 1) {
        const float2 r0 = unpack2(acc0[0]), r1 = unpack2(acc0[1]);
        const float2 r2 = unpack2(acc0[2]), r3 = unpack2(acc0[3]);
        const float2 s0r = unpack2(acc1[0]), s1r = unpack2(acc1[1]);
        const float2 s2r = unpack2(acc1[2]), s3r = unpack2(acc1[3]);
        *(float4*)(red)      = make_float4(r0.x, r0.y, r1.x, r1.y);
        *(float4*)(red + 4)  = make_float4(r2.x, r2.y, r3.x, r3.y);
        *(float4*)(red + 8)  = make_float4(s0r.x, s0r.y, s1r.x, s1r.y);
        *(float4*)(red + 12) = make_float4(s2r.x, s2r.y, s3r.x, s3r.y);
    }
    __syncthreads();
    if (half == 0) {
        const float4 p0 = *(const float4*)(red);
        const float4 p1 = *(const float4*)(red + 4);
        const float4 p2 = *(const float4*)(red + 8);
        const float4 p3 = *(const float4*)(red + 12);
        const float4 bv_0 = *(const float4*)(bias + tx * 8);
        const float4 bv_1 = *(const float4*)(bias + tx * 8 + 4);
        {
            const float2 r0 = unpack2(acc0[0]), r1 = unpack2(acc0[1]);
            const float2 r2 = unpack2(acc0[2]), r3 = unpack2(acc0[3]);
            float* o1 = out + (size_t)(bv0 + ty) * OO + tx * 8;
            *(float4*)(o1)     = make_float4(r0.x + p0.x + bv_0.x, r0.y + p0.y + bv_0.y,
                                             r1.x + p0.z + bv_0.z, r1.y + p0.w + bv_0.w);
            *(float4*)(o1 + 4) = make_float4(r2.x + p1.x + bv_1.x, r2.y + p1.y + bv_1.y,
                                             r3.x + p1.z + bv_1.z, r3.y + p1.w + bv_1.w);
        }
        {
            const float2 r0 = unpack2(acc1[0]), r1 = unpack2(acc1[1]);
            const float2 r2 = unpack2(acc1[2]), r3 = unpack2(acc1[3]);
            float* o2 = out + (size_t)(bv0 + ty + 32) * OO + tx * 8;
            *(float4*)(o2)     = make_float4(r0.x + p2.x + bv_0.x, r0.y + p2.y + bv_0.y,
                                             r1.x + p2.z + bv_0.z, r1.y + p2.w + bv_0.w);
            *(float4*)(o2 + 4) = make_float4(r2.x + p3.x + bv_1.x, r2.y + p3.y + bv_1.y,
                                             r3.x + p3.z + bv_1.z, r3.y + p3.w + bv_1.w);
        }
    }
}

// ---------------------------------------------------------------------------
// Host launcher (graph-capturable: kernel launches only)
// ---------------------------------------------------------------------------
extern "C" void kernel_launch(void* const* d_in, const int* in_sizes, int n_in,
                              void* d_out, int out_size) {
    const float* x   = (const float*)d_in[0];  // [B,N,C]
    const int*   adj = (const int*)  d_in[1];  // [B,N,K]
    const float* W   = (const float*)d_in[2];  // [M,O,C]
    const float* b   = (const float*)d_in[3];  // [O]
    const float* u   = (const float*)d_in[4];  // [M,C]
    const float* v   = (const float*)d_in[5];  // [M,C]
    const float* c   = (const float*)d_in[6];  // [M]
    float* out = (float*)d_out;

    feast_wt<<<(MM * OO * CC + 255) / 256, 256>>>(W);
    feast_uvx<<<NVT / 8, 256>>>(x, u, v, c);

    const size_t smem_bytes =
        (size_t)(VTILE * SST + 2 * WCHUNK * 64 + 6144) * sizeof(float);  // 222208 B
    cudaFuncSetAttribute(feast_main, cudaFuncAttributeMaxDynamicSharedMemorySize,
                         (int)smem_bytes);
    feast_main<<<NVT / VTILE, NTHREADS, smem_bytes>>>(x, adj, b, out);
}

// round 3
// speedup vs baseline: 2.0616x; 1.2497x over previous
#include <cuda_runtime.h>
#include <cstdint>
#include <cstddef>

// Problem constants (fixed by the dataset)
#define NV    20000            // vertices per batch
#define NVT   80000            // B * N
#define KN    16               // neighbors
#define MM    9                // kernels
#define CC    64               // in channels
#define OO    64               // out channels

#define SST    584             // s_sm row stride (576 + 8)
#define VTILE  32              // vertices per block
#define WCHUNK 72              // K-rows per staged Wt chunk (288 = 4 * 72 per half)
#define NTHREADS 256

// Device-global scratch (sanctioned workaround for no-alloc rule)
__device__ float g_uxc[NVT * 12];     // ux + c, padded to 12 floats/vertex
__device__ float g_vxp[NVT * 12];     // vx, padded to 12 floats/vertex
__device__ float g_wt[576 * 64];      // W transposed: Wt[m*64+c][o]

// ---- packed fp32x2 helpers (Blackwell; ptxas won't auto-fuse these) ----
__device__ __forceinline__ void fma2(unsigned long long& acc,
                                     unsigned long long a,
                                     unsigned long long b) {
    asm("fma.rn.f32x2 %0, %1, %2, %0;" : "+l"(acc) : "l"(a), "l"(b));
}
__device__ __forceinline__ unsigned long long pack2(float x, float y) {
    unsigned long long r;
    asm("mov.b64 %0, {%1, %2};" : "=l"(r) : "f"(x), "f"(y));
    return r;
}
__device__ __forceinline__ float2 unpack2(unsigned long long a) {
    float2 r;
    asm("mov.b64 {%0, %1}, %2;" : "=f"(r.x), "=f"(r.y) : "l"(a));
    return r;
}

// ---------------------------------------------------------------------------
// Kernel 1 (merged prep): blocks [0, NVT/8)  -> per-vertex u/v projections
//                         blocks [NVT/8, +144) -> W transpose
// ---------------------------------------------------------------------------
#define UVX_BLOCKS (NVT / 8)

__global__ void __launch_bounds__(256)
feast_prep(const float* __restrict__ x, const float* __restrict__ u,
           const float* __restrict__ v, const float* __restrict__ c,
           const float* __restrict__ W) {
    if (blockIdx.x < UVX_BLOCKS) {
        const int wid  = threadIdx.x >> 5;
        const int lane = threadIdx.x & 31;
        const int gi   = blockIdx.x * 8 + wid;

        const float2 xx = *(const float2*)(x + (size_t)gi * CC + lane * 2);
        #pragma unroll
        for (int m = 0; m < MM; ++m) {
            const float2 uu = *(const float2*)(u + m * CC + lane * 2);
            const float2 vv = *(const float2*)(v + m * CC + lane * 2);
            float pu = xx.x * uu.x + xx.y * uu.y;
            float pv = xx.x * vv.x + xx.y * vv.y;
            #pragma unroll
            for (int off = 16; off > 0; off >>= 1) {
                pu += __shfl_xor_sync(0xffffffffu, pu, off);
                pv += __shfl_xor_sync(0xffffffffu, pv, off);
            }
            if (lane == 0) {
                g_uxc[gi * 12 + m] = pu + c[m];
                g_vxp[gi * 12 + m] = pv;
            }
        }
    } else {
        int tid = (blockIdx.x - UVX_BLOCKS) * 256 + threadIdx.x;
        if (tid >= MM * OO * CC) return;
        int cc = tid & 63;
        int o  = (tid >> 6) & 63;
        int m  = tid >> 12;
        g_wt[(m * 64 + cc) * 64 + o] = W[tid];
    }
}

// ---------------------------------------------------------------------------
// Kernel 2: fused gather + softmax + s-accumulate + [32,576]x[576,64] GEMM
// 256 threads, 2 CTAs/SM. Phase 2 split-K: half h covers K rows [h*288, h*288+288).
// ---------------------------------------------------------------------------
__global__ void __launch_bounds__(NTHREADS, 2)
feast_main(const float* __restrict__ x, const int* __restrict__ adj,
           const float* __restrict__ bias, float* __restrict__ out) {
    extern __shared__ float sm[];
    float* s_sm  = sm;                         // VTILE * SST = 18688 floats
    float* wt_sm = sm + VTILE * SST;           // 2 * 72 * 64 = 9216 floats

    const int tid  = threadIdx.x;
    const int w    = tid >> 5;
    const int lane = tid & 31;
    const int kk   = lane & 15;                 // neighbor slot for stage A
    const int vp   = lane >> 4;                 // vertex-of-pair for stage A
    const int bv0  = blockIdx.x * VTILE;
    float* qbuf = wt_sm + w * 384;              // wt_sm is dead during phase 1

    // ======================= PHASE 1 =======================
    // 8 warps x 2 iterations x 2 vertices = 32 vertices
    #pragma unroll
    for (int it = 0; it < 2; ++it) {
        const int vpair = w * 4 + it * 2;

        // ---- stage A: lane (vp, kk) -> softmax over M for one neighbor ----
        const int giA  = bv0 + vpair + vp;
        const int base = (giA / NV) * NV;
        const int a    = adj[giA * KN + kk];
        const unsigned bal = __ballot_sync(0xffffffffu, a > 0);
        const int deg0 = __popc(bal & 0xffffu);
        const int deg1 = __popc(bal >> 16);
        const float validf = (a > 0) ? 1.0f : 0.0f;
        const int j0 = (a > 0) ? (base + a - 1) : base;   // always a valid row

        const float4 uc0 = *(const float4*)(g_uxc + giA * 12);
        const float4 uc1 = *(const float4*)(g_uxc + giA * 12 + 4);
        const float4 uc2 = *(const float4*)(g_uxc + giA * 12 + 8);
        const float4 vv0 = *(const float4*)(g_vxp + j0 * 12);
        const float4 vv1 = *(const float4*)(g_vxp + j0 * 12 + 4);
        const float4 vv2 = *(const float4*)(g_vxp + j0 * 12 + 8);
        float l[9];
        l[0] = (uc0.x + vv0.x) * validf; l[1] = (uc0.y + vv0.y) * validf;
        l[2] = (uc0.z + vv0.z) * validf; l[3] = (uc0.w + vv0.w) * validf;
        l[4] = (uc1.x + vv1.x) * validf; l[5] = (uc1.y + vv1.y) * validf;
        l[6] = (uc1.z + vv1.z) * validf; l[7] = (uc1.w + vv1.w) * validf;
        l[8] = (uc2.x + vv2.x) * validf;
        float mx = l[0];
        #pragma unroll
        for (int m = 1; m < 9; ++m) mx = fmaxf(mx, l[m]);
        float e[9], ssum = 0.f;
        #pragma unroll
        for (int m = 0; m < 9; ++m) { e[m] = __expf(l[m] - mx); ssum += e[m]; }
        float r;
        asm("rcp.approx.f32 %0, %1;" : "=f"(r) : "f"(ssum));
        r *= validf;                                  // invalid neighbor -> q = 0

        float* qk = qbuf + (vp * 16 + kk) * 12;
        *(float4*)(qk)     = make_float4(e[0]*r, e[1]*r, e[2]*r, e[3]*r);
        *(float4*)(qk + 4) = make_float4(e[4]*r, e[5]*r, e[6]*r, e[7]*r);
        *(float4*)(qk + 8) = make_float4(e[8]*r, __int_as_float(j0), 0.f, 0.f);
        __syncwarp();

        // ---- stage B: lane <-> channels (lane, lane+32); branchless gathers ----
        #pragma unroll
        for (int vsel = 0; vsel < 2; ++vsel) {
            const float* qb = qbuf + vsel * 192;
            unsigned long long accA[4] = {0ull,0ull,0ull,0ull};
            unsigned long long accB[4] = {0ull,0ull,0ull,0ull};
            float acc8a = 0.f, acc8b = 0.f;
            #pragma unroll 8
            for (int k2 = 0; k2 < KN; ++k2) {
                const ulonglong2 qp0 = *(const ulonglong2*)(qb + k2 * 12);
                const ulonglong2 qp1 = *(const ulonglong2*)(qb + k2 * 12 + 4);
                const float2     qt  = *(const float2*)(qb + k2 * 12 + 8);
                const int j2 = __float_as_int(qt.y);      // always valid; q==0 if pad
                const float x0 = x[j2 * CC + lane];
                const float x1 = x[j2 * CC + lane + 32];
                const unsigned long long xx0 = pack2(x0, x0);
                const unsigned long long xx1 = pack2(x1, x1);
                fma2(accA[0], qp0.x, xx0); fma2(accA[1], qp0.y, xx0);
                fma2(accA[2], qp1.x, xx0); fma2(accA[3], qp1.y, xx0);
                fma2(accB[0], qp0.x, xx1); fma2(accB[1], qp0.y, xx1);
                fma2(accB[2], qp1.x, xx1); fma2(accB[3], qp1.y, xx1);
                acc8a = fmaf(qt.x, x0, acc8a);
                acc8b = fmaf(qt.x, x1, acc8b);
            }
            const int dg = vsel ? deg1 : deg0;
            const float scl = (dg > 0) ? (1.0f / (float)dg) : 0.0f;
            float* srow = s_sm + (vpair + vsel) * SST;
            #pragma unroll
            for (int mp = 0; mp < 4; ++mp) {
                const float2 a0 = unpack2(accA[mp]);
                const float2 b0 = unpack2(accB[mp]);
                srow[(2*mp)   * 64 + lane]      = a0.x * scl;
                srow[(2*mp+1) * 64 + lane]      = a0.y * scl;
                srow[(2*mp)   * 64 + lane + 32] = b0.x * scl;
                srow[(2*mp+1) * 64 + lane + 32] = b0.y * scl;
            }
            srow[8 * 64 + lane]      = acc8a * scl;
            srow[8 * 64 + lane + 32] = acc8b * scl;
        }
        __syncwarp();
    }

    // ======================= PHASE 2: out = s @ Wt + b (split-K) ===========
    const int half = tid >> 7;                 // 0 or 1
    const int t    = tid & 127;
    const int tx   = t & 7;                    // 8 output cols (o = tx*8 .. +7)
    const int ty   = t >> 3;                   // rows ty and ty+16
    float* mybuf = wt_sm + half * (WCHUNK * 64);
    const float* s0 = s_sm + ty * SST + half * 288;
    const float* s1 = s_sm + (ty + 16) * SST + half * 288;
    unsigned long long acc0[4] = {0ull,0ull,0ull,0ull};
    unsigned long long acc1[4] = {0ull,0ull,0ull,0ull};

    const float* gbase = g_wt + half * (288 * 64);
    float4 pre[9];
    {
        const float4* src = (const float4*)gbase;
        #pragma unroll
        for (int i = 0; i < 9; ++i) pre[i] = src[t + i * 128];
    }

    for (int ch = 0; ch < 4; ++ch) {
        __syncthreads();   // q reads (ch 0) / prior compute done before store
        // store prefetched chunk, bank-conflict-free permutation:
        // float4 jj of a 64-float row -> position (jj&1)*8 + (jj>>1)
        #pragma unroll
        for (int i = 0; i < 9; ++i) {
            const int idx = t + i * 128;           // float4 index within chunk
            const int kr  = idx >> 4;
            const int jj  = idx & 15;
            const int dpos = kr * 16 + (jj & 1) * 8 + (jj >> 1);
            ((float4*)mybuf)[dpos] = pre[i];
        }
        __syncthreads();

        if (ch < 3) {
            const float4* src = (const float4*)(gbase + (ch + 1) * (WCHUNK * 64));
            #pragma unroll
            for (int i = 0; i < 9; ++i) pre[i] = src[t + i * 128];
        }

        const float* sa = s0 + ch * WCHUNK;
        const float* sb = s1 + ch * WCHUNK;
        #pragma unroll 4
        for (int kr = 0; kr < WCHUNK; kr += 2) {
            const float2 a2 = *(const float2*)(sa + kr);
            const float2 b2 = *(const float2*)(sb + kr);
            #pragma unroll
            for (int q = 0; q < 2; ++q) {
                const float av = q ? a2.y : a2.x;
                const float bv = q ? b2.y : b2.x;
                const unsigned long long pa = pack2(av, av);
                const unsigned long long pb = pack2(bv, bv);
                const float* row = mybuf + (kr + q) * 64;
                const ulonglong2 wA = *(const ulonglong2*)(row + tx * 4);       // o: 8tx..+3
                const ulonglong2 wB = *(const ulonglong2*)(row + 32 + tx * 4);  // o: 8tx+4..+7
                fma2(acc0[0], pa, wA.x); fma2(acc0[1], pa, wA.y);
                fma2(acc0[2], pa, wB.x); fma2(acc0[3], pa, wB.y);
                fma2(acc1[0], pb, wA.x); fma2(acc1[1], pb, wA.y);
                fma2(acc1[2], pb, wB.x); fma2(acc1[3], pb, wB.y);
            }
        }
    }
    __syncthreads();

    // ---- reduce the two K-halves (reuse wt_sm as the exchange buffer) ----
    float* red = wt_sm + t * 16;
    if (half == 1) {
        const float2 r0 = unpack2(acc0[0]), r1 = unpack2(acc0[1]);
        const float2 r2 = unpack2(acc0[2]), r3 = unpack2(acc0[3]);
        const float2 u0 = unpack2(acc1[0]), u1 = unpack2(acc1[1]);
        const float2 u2 = unpack2(acc1[2]), u3 = unpack2(acc1[3]);
        *(float4*)(red)      = make_float4(r0.x, r0.y, r1.x, r1.y);
        *(float4*)(red + 4)  = make_float4(r2.x, r2.y, r3.x, r3.y);
        *(float4*)(red + 8)  = make_float4(u0.x, u0.y, u1.x, u1.y);
        *(float4*)(red + 12) = make_float4(u2.x, u2.y, u3.x, u3.y);
    }
    __syncthreads();
    if (half == 0) {
        const float4 p0 = *(const float4*)(red);
        const float4 p1 = *(const float4*)(red + 4);
        const float4 p2 = *(const float4*)(red + 8);
        const float4 p3 = *(const float4*)(red + 12);
        const float4 bv_0 = *(const float4*)(bias + tx * 8);
        const float4 bv_1 = *(const float4*)(bias + tx * 8 + 4);
        {
            const float2 r0 = unpack2(acc0[0]), r1 = unpack2(acc0[1]);
            const float2 r2 = unpack2(acc0[2]), r3 = unpack2(acc0[3]);
            float* o1 = out + (size_t)(bv0 + ty) * OO + tx * 8;
            *(float4*)(o1)     = make_float4(r0.x + p0.x + bv_0.x, r0.y + p0.y + bv_0.y,
                                             r1.x + p0.z + bv_0.z, r1.y + p0.w + bv_0.w);
            *(float4*)(o1 + 4) = make_float4(r2.x + p1.x + bv_1.x, r2.y + p1.y + bv_1.y,
                                             r3.x + p1.z + bv_1.z, r3.y + p1.w + bv_1.w);
        }
        {
            const float2 r0 = unpack2(acc1[0]), r1 = unpack2(acc1[1]);
            const float2 r2 = unpack2(acc1[2]), r3 = unpack2(acc1[3]);
            float* o2 = out + (size_t)(bv0 + ty + 16) * OO + tx * 8;
            *(float4*)(o2)     = make_float4(r0.x + p2.x + bv_0.x, r0.y + p2.y + bv_0.y,
                                             r1.x + p2.z + bv_0.z, r1.y + p2.w + bv_0.w);
            *(float4*)(o2 + 4) = make_float4(r2.x + p3.x + bv_1.x, r2.y + p3.y + bv_1.y,
                                             r3.x + p3.z + bv_1.z, r3.y + p3.w + bv_1.w);
        }
    }
}

// ---------------------------------------------------------------------------
// Host launcher (graph-capturable: kernel launches only)
// ---------------------------------------------------------------------------
extern "C" void kernel_launch(void* const* d_in, const int* in_sizes, int n_in,
                              void* d_out, int out_size) {
    const float* x   = (const float*)d_in[0];  // [B,N,C]
    const int*   adj = (const int*)  d_in[1];  // [B,N,K]
    const float* W   = (const float*)d_in[2];  // [M,O,C]
    const float* b   = (const float*)d_in[3];  // [O]
    const float* u   = (const float*)d_in[4];  // [M,C]
    const float* v   = (const float*)d_in[5];  // [M,C]
    const float* c   = (const float*)d_in[6];  // [M]
    float* out = (float*)d_out;

    feast_prep<<<UVX_BLOCKS + (MM * OO * CC + 255) / 256, 256>>>(x, u, v, c, W);

    const size_t smem_bytes =
        (size_t)(VTILE * SST + 2 * WCHUNK * 64) * sizeof(float);  // 111616 B
    cudaFuncSetAttribute(feast_main, cudaFuncAttributeMaxDynamicSharedMemorySize,
                         (int)smem_bytes);
    feast_main<<<NVT / VTILE, NTHREADS, smem_bytes>>>(x, adj, b, out);
}

// round 4
// speedup vs baseline: 2.4418x; 1.1844x over previous
#include <cuda_runtime.h>
#include <cstdint>
#include <cstddef>

// Problem constants (fixed by the dataset)
#define NV    20000            // vertices per batch
#define NVT   80000            // B * N
#define KN    16               // neighbors
#define MM    9                // kernels
#define CC    64               // in channels
#define OO    64               // out channels

#define SST    577             // s_sm row stride (odd -> row-group bank spread)
#define VTILE  32              // vertices per block
#define NTHREADS 256
#define S_FLOATS  (VTILE * SST)        // 18464 floats (also >= 256*68 for reduce)
#define WT_FLOATS (72 * 64)            // 4608 floats per staged window

// Device-global scratch (sanctioned workaround for no-alloc rule)
__device__ float g_uxc[NVT * 12];     // ux + c, padded to 12 floats/vertex
__device__ float g_vxp[NVT * 12];     // vx, padded to 12 floats/vertex
__device__ float g_wt[576 * 64];      // W transposed: Wt[m*64+c][o]

// ---- packed fp32x2 helpers (Blackwell; ptxas won't auto-fuse these) ----
__device__ __forceinline__ void fma2(unsigned long long& acc,
                                     unsigned long long a,
                                     unsigned long long b) {
    asm("fma.rn.f32x2 %0, %1, %2, %0;" : "+l"(acc) : "l"(a), "l"(b));
}
__device__ __forceinline__ void add2(unsigned long long& a, unsigned long long b) {
    asm("add.rn.f32x2 %0, %0, %1;" : "+l"(a) : "l"(b));
}
__device__ __forceinline__ unsigned long long pack2(float x, float y) {
    unsigned long long r;
    asm("mov.b64 %0, {%1, %2};" : "=l"(r) : "f"(x), "f"(y));
    return r;
}
__device__ __forceinline__ float2 unpack2(unsigned long long a) {
    float2 r;
    asm("mov.b64 {%0, %1}, %2;" : "=f"(r.x), "=f"(r.y) : "l"(a));
    return r;
}

// ---------------------------------------------------------------------------
// Kernel 1 (merged prep): blocks [0, NVT/8)  -> per-vertex u/v projections
//                         blocks [NVT/8, +144) -> W transpose
// ---------------------------------------------------------------------------
#define UVX_BLOCKS (NVT / 8)

__global__ void __launch_bounds__(256)
feast_prep(const float* __restrict__ x, const float* __restrict__ u,
           const float* __restrict__ v, const float* __restrict__ c,
           const float* __restrict__ W) {
    if (blockIdx.x < UVX_BLOCKS) {
        const int wid  = threadIdx.x >> 5;
        const int lane = threadIdx.x & 31;
        const int gi   = blockIdx.x * 8 + wid;

        const float2 xx = *(const float2*)(x + (size_t)gi * CC + lane * 2);
        #pragma unroll
        for (int m = 0; m < MM; ++m) {
            const float2 uu = *(const float2*)(u + m * CC + lane * 2);
            const float2 vv = *(const float2*)(v + m * CC + lane * 2);
            float pu = xx.x * uu.x + xx.y * uu.y;
            float pv = xx.x * vv.x + xx.y * vv.y;
            #pragma unroll
            for (int off = 16; off > 0; off >>= 1) {
                pu += __shfl_xor_sync(0xffffffffu, pu, off);
                pv += __shfl_xor_sync(0xffffffffu, pv, off);
            }
            if (lane == 0) {
                g_uxc[gi * 12 + m] = pu + c[m];
                g_vxp[gi * 12 + m] = pv;
            }
        }
    } else {
        int tid = (blockIdx.x - UVX_BLOCKS) * 256 + threadIdx.x;
        if (tid >= MM * OO * CC) return;
        int cc = tid & 63;
        int o  = (tid >> 6) & 63;
        int m  = tid >> 12;
        g_wt[(m * 64 + cc) * 64 + o] = W[tid];
    }
}

// ---------------------------------------------------------------------------
// Kernel 2: fused gather + softmax + s-accumulate + [32,576]x[576,64] GEMM
// Phase 2: warp = K-group (8-way split-K, 72 rows each); thread = 8x8 tile.
// ---------------------------------------------------------------------------
__global__ void __launch_bounds__(NTHREADS, 2)
feast_main(const float* __restrict__ x, const int* __restrict__ adj,
           const float* __restrict__ bias, float* __restrict__ out) {
    extern __shared__ float sm[];
    float* s_sm  = sm;                         // S_FLOATS
    float* wt_sm = sm + S_FLOATS;              // WT_FLOATS (q scratch in phase 1)

    const int tid  = threadIdx.x;
    const int w    = tid >> 5;
    const int lane = tid & 31;
    const int kk   = lane & 15;                 // neighbor slot for stage A
    const int vp   = lane >> 4;                 // vertex-of-pair for stage A
    const int bv0  = blockIdx.x * VTILE;
    float* qbuf = wt_sm + w * 384;              // wt_sm is dead during phase 1

    // initial prefetch of wt window 0 (overlaps all of phase 1)
    float4 pre[5];
    #pragma unroll
    for (int i = 0; i < 4; ++i) pre[i] = ((const float4*)g_wt)[tid + i * 256];
    pre[4] = (tid < 128) ? ((const float4*)g_wt)[tid + 1024] : make_float4(0,0,0,0);

    // ======================= PHASE 1 =======================
    #pragma unroll
    for (int it = 0; it < 2; ++it) {
        const int vpair = w * 4 + it * 2;

        // ---- stage A: lane (vp, kk) -> softmax over M for one neighbor ----
        const int giA  = bv0 + vpair + vp;
        const int base = (giA / NV) * NV;
        const int a    = adj[giA * KN + kk];
        const unsigned bal = __ballot_sync(0xffffffffu, a > 0);
        const int deg0 = __popc(bal & 0xffffu);
        const int deg1 = __popc(bal >> 16);
        const float validf = (a > 0) ? 1.0f : 0.0f;
        const int j0 = (a > 0) ? (base + a - 1) : base;   // always a valid row

        const float4 uc0 = *(const float4*)(g_uxc + giA * 12);
        const float4 uc1 = *(const float4*)(g_uxc + giA * 12 + 4);
        const float4 uc2 = *(const float4*)(g_uxc + giA * 12 + 8);
        const float4 vv0 = *(const float4*)(g_vxp + j0 * 12);
        const float4 vv1 = *(const float4*)(g_vxp + j0 * 12 + 4);
        const float4 vv2 = *(const float4*)(g_vxp + j0 * 12 + 8);
        float l[9];
        l[0] = (uc0.x + vv0.x) * validf; l[1] = (uc0.y + vv0.y) * validf;
        l[2] = (uc0.z + vv0.z) * validf; l[3] = (uc0.w + vv0.w) * validf;
        l[4] = (uc1.x + vv1.x) * validf; l[5] = (uc1.y + vv1.y) * validf;
        l[6] = (uc1.z + vv1.z) * validf; l[7] = (uc1.w + vv1.w) * validf;
        l[8] = (uc2.x + vv2.x) * validf;
        float mx = l[0];
        #pragma unroll
        for (int m = 1; m < 9; ++m) mx = fmaxf(mx, l[m]);
        float e[9], ssum = 0.f;
        #pragma unroll
        for (int m = 0; m < 9; ++m) { e[m] = __expf(l[m] - mx); ssum += e[m]; }
        float r;
        asm("rcp.approx.f32 %0, %1;" : "=f"(r) : "f"(ssum));
        r *= validf;                                  // invalid neighbor -> q = 0

        float* qk = qbuf + (vp * 16 + kk) * 12;
        *(float4*)(qk)     = make_float4(e[0]*r, e[1]*r, e[2]*r, e[3]*r);
        *(float4*)(qk + 4) = make_float4(e[4]*r, e[5]*r, e[6]*r, e[7]*r);
        *(float4*)(qk + 8) = make_float4(e[8]*r, __int_as_float(j0), 0.f, 0.f);
        __syncwarp();

        // ---- stage B: lane <-> channels (lane, lane+32); branchless gathers ----
        #pragma unroll
        for (int vsel = 0; vsel < 2; ++vsel) {
            const float* qb = qbuf + vsel * 192;
            unsigned long long accA[4] = {0ull,0ull,0ull,0ull};
            unsigned long long accB[4] = {0ull,0ull,0ull,0ull};
            float acc8a = 0.f, acc8b = 0.f;
            #pragma unroll 8
            for (int k2 = 0; k2 < KN; ++k2) {
                const ulonglong2 qp0 = *(const ulonglong2*)(qb + k2 * 12);
                const ulonglong2 qp1 = *(const ulonglong2*)(qb + k2 * 12 + 4);
                const float2     qt  = *(const float2*)(qb + k2 * 12 + 8);
                const int j2 = __float_as_int(qt.y);      // always valid; q==0 if pad
                const float x0 = x[j2 * CC + lane];
                const float x1 = x[j2 * CC + lane + 32];
                const unsigned long long xx0 = pack2(x0, x0);
                const unsigned long long xx1 = pack2(x1, x1);
                fma2(accA[0], qp0.x, xx0); fma2(accA[1], qp0.y, xx0);
                fma2(accA[2], qp1.x, xx0); fma2(accA[3], qp1.y, xx0);
                fma2(accB[0], qp0.x, xx1); fma2(accB[1], qp0.y, xx1);
                fma2(accB[2], qp1.x, xx1); fma2(accB[3], qp1.y, xx1);
                acc8a = fmaf(qt.x, x0, acc8a);
                acc8b = fmaf(qt.x, x1, acc8b);
            }
            const int dg = vsel ? deg1 : deg0;
            const float scl = (dg > 0) ? (1.0f / (float)dg) : 0.0f;
            float* srow = s_sm + (vpair + vsel) * SST;
            #pragma unroll
            for (int mp = 0; mp < 4; ++mp) {
                const float2 a0 = unpack2(accA[mp]);
                const float2 b0 = unpack2(accB[mp]);
                srow[(2*mp)   * 64 + lane]      = a0.x * scl;
                srow[(2*mp+1) * 64 + lane]      = a0.y * scl;
                srow[(2*mp)   * 64 + lane + 32] = b0.x * scl;
                srow[(2*mp+1) * 64 + lane + 32] = b0.y * scl;
            }
            srow[8 * 64 + lane]      = acc8a * scl;
            srow[8 * 64 + lane + 32] = acc8b * scl;
        }
        __syncwarp();
    }

    // ======================= PHASE 2 =======================
    // warp kg handles K rows [w*72 + kg*9, +9) per window w; lane -> 8x8 tile
    const int kg = w;                         // K-group == warp
    const int cg = lane & 7;                  // col group: o = cg*8 .. +7
    const int rg = lane >> 3;                 // row group: rows rg*8 .. +7
    const int swz = cg >> 2;                  // bank-swizzle select
    const int offLo = (2 * cg + swz) * 4;     // quad holding cols 8cg..+3
    const int offHi = (2 * cg + 1 - swz) * 4; // quad holding cols 8cg+4..+7

    unsigned long long acc[8][4];
    #pragma unroll
    for (int i = 0; i < 8; ++i)
        #pragma unroll
        for (int p = 0; p < 4; ++p) acc[i][p] = 0ull;

    const float* sbase = s_sm + rg * 8 * SST + kg * 9;

    for (int wnd = 0; wnd < 8; ++wnd) {
        __syncthreads();   // wt_sm (q / previous window) free to overwrite
        // store staged window with quad swizzle: float4 j -> j ^ (j>>3)
        #pragma unroll
        for (int i = 0; i < 5; ++i) {
            const int idx = tid + i * 256;
            if (idx < 1152) {
                const int kr = idx >> 4, j = idx & 15;
                ((float4*)wt_sm)[kr * 16 + (j ^ (j >> 3))] = pre[i];
            }
        }
        __syncthreads();

        if (wnd < 7) {
            const float4* src = (const float4*)(g_wt + (wnd + 1) * WT_FLOATS);
            #pragma unroll
            for (int i = 0; i < 5; ++i) {
                const int idx = tid + i * 256;
                if (idx < 1152) pre[i] = src[idx];
            }
        }

        const float* sk = sbase + wnd * 72;
        #pragma unroll 3
        for (int kr = 0; kr < 9; ++kr) {
            const float* wrow = wt_sm + (kg * 9 + kr) * 64;
            const ulonglong2 wLo = *(const ulonglong2*)(wrow + offLo); // c0..c3
            const ulonglong2 wHi = *(const ulonglong2*)(wrow + offHi); // c4..c7
            #pragma unroll
            for (int i = 0; i < 8; ++i) {
                const float sv = sk[i * SST + kr];
                const unsigned long long ss = pack2(sv, sv);
                fma2(acc[i][0], ss, wLo.x);
                fma2(acc[i][1], ss, wLo.y);
                fma2(acc[i][2], ss, wHi.x);
                fma2(acc[i][3], ss, wHi.y);
            }
        }
    }
    __syncthreads();   // all s_sm reads done; safe to reuse for partials

    // ---- stash 64 partial floats per thread in s_sm (stride 68) ----
    {
        float* pb = s_sm + tid * 68;
        #pragma unroll
        for (int i = 0; i < 8; ++i) {
            ulonglong2 t0; t0.x = acc[i][0]; t0.y = acc[i][1];
            ulonglong2 t1; t1.x = acc[i][2]; t1.y = acc[i][3];
            *(ulonglong2*)(pb + i * 8)     = t0;
            *(ulonglong2*)(pb + i * 8 + 4) = t1;
        }
    }
    __syncthreads();

    // ---- reduce 8 K-groups; thread -> (row r, cols cs*8..+7) ----
    {
        const int r  = tid >> 3;
        const int cs = tid & 7;
        const int rgp = r >> 3, ii = r & 7;
        unsigned long long p0 = 0, p1 = 0, p2 = 0, p3 = 0;
        #pragma unroll
        for (int g = 0; g < 8; ++g) {
            const float* pb = s_sm + (g * 32 + rgp * 8 + cs) * 68 + ii * 8;
            const ulonglong2 a = *(const ulonglong2*)(pb);
            const ulonglong2 b = *(const ulonglong2*)(pb + 4);
            add2(p0, a.x); add2(p1, a.y); add2(p2, b.x); add2(p3, b.y);
        }
        const float4 bv_0 = *(const float4*)(bias + cs * 8);
        const float4 bv_1 = *(const float4*)(bias + cs * 8 + 4);
        const float2 f0 = unpack2(p0), f1 = unpack2(p1);
        const float2 f2 = unpack2(p2), f3 = unpack2(p3);
        float* op = out + (size_t)(bv0 + r) * OO + cs * 8;
        *(float4*)(op)     = make_float4(f0.x + bv_0.x, f0.y + bv_0.y,
                                         f1.x + bv_0.z, f1.y + bv_0.w);
        *(float4*)(op + 4) = make_float4(f2.x + bv_1.x, f2.y + bv_1.y,
                                         f3.x + bv_1.z, f3.y + bv_1.w);
    }
}

// ---------------------------------------------------------------------------
// Host launcher (graph-capturable: kernel launches only)
// ---------------------------------------------------------------------------
extern "C" void kernel_launch(void* const* d_in, const int* in_sizes, int n_in,
                              void* d_out, int out_size) {
    const float* x   = (const float*)d_in[0];  // [B,N,C]
    const int*   adj = (const int*)  d_in[1];  // [B,N,K]
    const float* W   = (const float*)d_in[2];  // [M,O,C]
    const float* b   = (const float*)d_in[3];  // [O]
    const float* u   = (const float*)d_in[4];  // [M,C]
    const float* v   = (const float*)d_in[5];  // [M,C]
    const float* c   = (const float*)d_in[6];  // [M]
    float* out = (float*)d_out;

    feast_prep<<<UVX_BLOCKS + (MM * OO * CC + 255) / 256, 256>>>(x, u, v, c, W);

    const size_t smem_bytes = (size_t)(S_FLOATS + WT_FLOATS) * sizeof(float); // 92288
    cudaFuncSetAttribute(feast_main, cudaFuncAttributeMaxDynamicSharedMemorySize,
                         (int)smem_bytes);
    feast_main<<<NVT / VTILE, NTHREADS, smem_bytes>>>(x, adj, b, out);
}

// round 5
// speedup vs baseline: 2.4584x; 1.0068x over previous
#include <cuda_runtime.h>
#include <cstdint>
#include <cstddef>

// Problem constants (fixed by the dataset)
#define NV    20000            // vertices per batch
#define NVT   80000            // B * N
#define KN    16               // neighbors
#define MM    9                // kernels
#define CC    64               // in channels
#define OO    64               // out channels

#define SST    577             // s_sm row stride (odd -> row-group bank spread)
#define VTILE  32              // vertices per block
#define NTHREADS 256
#define S_FLOATS  (VTILE * SST)        // 18464 floats (also >= 256*68 for reduce)
#define WT_FLOATS (72 * 64)            // 4608 floats per wt window buffer

// Device-global scratch (sanctioned workaround for no-alloc rule)
__device__ float g_uxc[NVT * 12];     // ux + c, padded to 12 floats/vertex
__device__ float g_vxp[NVT * 12];     // vx, padded to 12 floats/vertex
__device__ float g_wt[576 * 64];      // W transposed: Wt[m*64+c][o]

// ---- packed fp32x2 helpers (Blackwell; ptxas won't auto-fuse these) ----
__device__ __forceinline__ void fma2(unsigned long long& acc,
                                     unsigned long long a,
                                     unsigned long long b) {
    asm("fma.rn.f32x2 %0, %1, %2, %0;" : "+l"(acc) : "l"(a), "l"(b));
}
__device__ __forceinline__ void add2(unsigned long long& a, unsigned long long b) {
    asm("add.rn.f32x2 %0, %0, %1;" : "+l"(a) : "l"(b));
}
__device__ __forceinline__ unsigned long long pack2(float x, float y) {
    unsigned long long r;
    asm("mov.b64 %0, {%1, %2};" : "=l"(r) : "f"(x), "f"(y));
    return r;
}
__device__ __forceinline__ float2 unpack2(unsigned long long a) {
    float2 r;
    asm("mov.b64 {%0, %1}, %2;" : "=f"(r.x), "=f"(r.y) : "l"(a));
    return r;
}
// ---- cp.async helpers ----
__device__ __forceinline__ void cpa16(uint32_t dst_smem, const void* src) {
    asm volatile("cp.async.cg.shared.global [%0], [%1], 16;"
                 :: "r"(dst_smem), "l"(src));
}
__device__ __forceinline__ void cpa_commit() {
    asm volatile("cp.async.commit_group;");
}
__device__ __forceinline__ void cpa_wait0() {
    asm volatile("cp.async.wait_group 0;");
}

// ---------------------------------------------------------------------------
// Kernel 1 (merged prep): blocks [0, NVT/8)  -> per-vertex u/v projections
//                         blocks [NVT/8, +144) -> W transpose
// ---------------------------------------------------------------------------
#define UVX_BLOCKS (NVT / 8)

__global__ void __launch_bounds__(256)
feast_prep(const float* __restrict__ x, const float* __restrict__ u,
           const float* __restrict__ v, const float* __restrict__ c,
           const float* __restrict__ W) {
    if (blockIdx.x < UVX_BLOCKS) {
        const int wid  = threadIdx.x >> 5;
        const int lane = threadIdx.x & 31;
        const int gi   = blockIdx.x * 8 + wid;

        const float2 xx = *(const float2*)(x + (size_t)gi * CC + lane * 2);
        #pragma unroll
        for (int m = 0; m < MM; ++m) {
            const float2 uu = *(const float2*)(u + m * CC + lane * 2);
            const float2 vv = *(const float2*)(v + m * CC + lane * 2);
            float pu = xx.x * uu.x + xx.y * uu.y;
            float pv = xx.x * vv.x + xx.y * vv.y;
            #pragma unroll
            for (int off = 16; off > 0; off >>= 1) {
                pu += __shfl_xor_sync(0xffffffffu, pu, off);
                pv += __shfl_xor_sync(0xffffffffu, pv, off);
            }
            if (lane == 0) {
                g_uxc[gi * 12 + m] = pu + c[m];
                g_vxp[gi * 12 + m] = pv;
            }
        }
    } else {
        int tid = (blockIdx.x - UVX_BLOCKS) * 256 + threadIdx.x;
        if (tid >= MM * OO * CC) return;
        int cc = tid & 63;
        int o  = (tid >> 6) & 63;
        int m  = tid >> 12;
        g_wt[(m * 64 + cc) * 64 + o] = W[tid];
    }
}

// ---------------------------------------------------------------------------
// Kernel 2: fused gather + softmax + s-accumulate + [32,576]x[576,64] GEMM
// Phase 2: warp = K-group (8-way split-K, 72 rows each); thread = 8x8 tile.
// wt windows double-buffered via cp.async (no registers, no staging stores).
// ---------------------------------------------------------------------------
__global__ void __launch_bounds__(NTHREADS, 2)
feast_main(const float* __restrict__ x, const int* __restrict__ adj,
           const float* __restrict__ bias, float* __restrict__ out) {
    extern __shared__ float sm[];
    float* s_sm = sm;                          // S_FLOATS
    float* wt0  = sm + S_FLOATS;               // WT_FLOATS (buffer 0)
    float* wt1  = wt0 + WT_FLOATS;             // WT_FLOATS (buffer 1; q scratch)

    const int tid  = threadIdx.x;
    const int w    = tid >> 5;
    const int lane = tid & 31;
    const int kk   = lane & 15;                 // neighbor slot for stage A
    const int vp   = lane >> 4;                 // vertex-of-pair for stage A
    const int bv0  = blockIdx.x * VTILE;
    float* qbuf = wt1 + w * 384;                // wt1 is dead during phase 1

    // kick off wt window 0 -> wt0 (flows in under phase 1)
    {
        const uint32_t dst0 = (uint32_t)__cvta_generic_to_shared(wt0);
        #pragma unroll
        for (int i = 0; i < 5; ++i) {
            const int idx = tid + i * 256;
            if (idx < WT_FLOATS / 4)
                cpa16(dst0 + idx * 16, (const char*)g_wt + idx * 16);
        }
        cpa_commit();
    }

    // ======================= PHASE 1 =======================
    #pragma unroll
    for (int it = 0; it < 2; ++it) {
        const int vpair = w * 4 + it * 2;

        // ---- stage A: lane (vp, kk) -> softmax over M for one neighbor ----
        const int giA  = bv0 + vpair + vp;
        const int base = (giA / NV) * NV;
        const int a    = adj[giA * KN + kk];
        const unsigned bal = __ballot_sync(0xffffffffu, a > 0);
        const int deg0 = __popc(bal & 0xffffu);
        const int deg1 = __popc(bal >> 16);
        const float validf = (a > 0) ? 1.0f : 0.0f;
        const int j0 = (a > 0) ? (base + a - 1) : base;   // always a valid row

        const float4 uc0 = *(const float4*)(g_uxc + giA * 12);
        const float4 uc1 = *(const float4*)(g_uxc + giA * 12 + 4);
        const float4 uc2 = *(const float4*)(g_uxc + giA * 12 + 8);
        const float4 vv0 = *(const float4*)(g_vxp + j0 * 12);
        const float4 vv1 = *(const float4*)(g_vxp + j0 * 12 + 4);
        const float4 vv2 = *(const float4*)(g_vxp + j0 * 12 + 8);
        float l[9];
        l[0] = (uc0.x + vv0.x) * validf; l[1] = (uc0.y + vv0.y) * validf;
        l[2] = (uc0.z + vv0.z) * validf; l[3] = (uc0.w + vv0.w) * validf;
        l[4] = (uc1.x + vv1.x) * validf; l[5] = (uc1.y + vv1.y) * validf;
        l[6] = (uc1.z + vv1.z) * validf; l[7] = (uc1.w + vv1.w) * validf;
        l[8] = (uc2.x + vv2.x) * validf;
        float mx = l[0];
        #pragma unroll
        for (int m = 1; m < 9; ++m) mx = fmaxf(mx, l[m]);
        float e[9], ssum = 0.f;
        #pragma unroll
        for (int m = 0; m < 9; ++m) { e[m] = __expf(l[m] - mx); ssum += e[m]; }
        float r;
        asm("rcp.approx.f32 %0, %1;" : "=f"(r) : "f"(ssum));
        r *= validf;                                  // invalid neighbor -> q = 0

        float* qk = qbuf + (vp * 16 + kk) * 12;
        *(float4*)(qk)     = make_float4(e[0]*r, e[1]*r, e[2]*r, e[3]*r);
        *(float4*)(qk + 4) = make_float4(e[4]*r, e[5]*r, e[6]*r, e[7]*r);
        *(float4*)(qk + 8) = make_float4(e[8]*r, __int_as_float(j0), 0.f, 0.f);
        __syncwarp();

        // ---- stage B: lane <-> channels (lane, lane+32); branchless gathers ----
        #pragma unroll
        for (int vsel = 0; vsel < 2; ++vsel) {
            const float* qb = qbuf + vsel * 192;
            unsigned long long accA[4] = {0ull,0ull,0ull,0ull};
            unsigned long long accB[4] = {0ull,0ull,0ull,0ull};
            float acc8a = 0.f, acc8b = 0.f;
            #pragma unroll 8
            for (int k2 = 0; k2 < KN; ++k2) {
                const ulonglong2 qp0 = *(const ulonglong2*)(qb + k2 * 12);
                const ulonglong2 qp1 = *(const ulonglong2*)(qb + k2 * 12 + 4);
                const float2     qt  = *(const float2*)(qb + k2 * 12 + 8);
                const int j2 = __float_as_int(qt.y);      // always valid; q==0 if pad
                const float x0 = x[j2 * CC + lane];
                const float x1 = x[j2 * CC + lane + 32];
                const unsigned long long xx0 = pack2(x0, x0);
                const unsigned long long xx1 = pack2(x1, x1);
                fma2(accA[0], qp0.x, xx0); fma2(accA[1], qp0.y, xx0);
                fma2(accA[2], qp1.x, xx0); fma2(accA[3], qp1.y, xx0);
                fma2(accB[0], qp0.x, xx1); fma2(accB[1], qp0.y, xx1);
                fma2(accB[2], qp1.x, xx1); fma2(accB[3], qp1.y, xx1);
                acc8a = fmaf(qt.x, x0, acc8a);
                acc8b = fmaf(qt.x, x1, acc8b);
            }
            const int dg = vsel ? deg1 : deg0;
            const float scl = (dg > 0) ? (1.0f / (float)dg) : 0.0f;
            float* srow = s_sm + (vpair + vsel) * SST;
            #pragma unroll
            for (int mp = 0; mp < 4; ++mp) {
                const float2 a0 = unpack2(accA[mp]);
                const float2 b0 = unpack2(accB[mp]);
                srow[(2*mp)   * 64 + lane]      = a0.x * scl;
                srow[(2*mp+1) * 64 + lane]      = a0.y * scl;
                srow[(2*mp)   * 64 + lane + 32] = b0.x * scl;
                srow[(2*mp+1) * 64 + lane + 32] = b0.y * scl;
            }
            srow[8 * 64 + lane]      = acc8a * scl;
            srow[8 * 64 + lane + 32] = acc8b * scl;
        }
        __syncwarp();
    }
    __syncthreads();   // phase 1 done: s_sm complete, qbuf (wt1) reads done

    // ======================= PHASE 2 =======================
    // warp kg handles K rows [kg*9, +9) of each 72-row window; lane -> 8x8 tile
    const int kg = w;                         // K-group == warp
    const int cg = lane & 7;                  // col group: cols {4cg..+3, 32+4cg..+3}
    const int rg = lane >> 3;                 // row group: rows rg*8 .. +7

    unsigned long long acc[8][4];
    #pragma unroll
    for (int i = 0; i < 8; ++i)
        #pragma unroll
        for (int p = 0; p < 4; ++p) acc[i][p] = 0ull;

    const float* sbase = s_sm + rg * 8 * SST + kg * 9;
    float* bufs[2] = { wt0, wt1 };

    for (int wnd = 0; wnd < 8; ++wnd) {
        cpa_wait0();       // window wnd resident in bufs[wnd&1]
        __syncthreads();   // visible to all; prior compute on the other buf done

        if (wnd < 7) {     // prefetch wnd+1 into the other buffer
            const uint32_t dst =
                (uint32_t)__cvta_generic_to_shared(bufs[(wnd + 1) & 1]);
            const char* src = (const char*)(g_wt + (wnd + 1) * WT_FLOATS);
            #pragma unroll
            for (int i = 0; i < 5; ++i) {
                const int idx = tid + i * 256;
                if (idx < WT_FLOATS / 4) cpa16(dst + idx * 16, src + idx * 16);
            }
            cpa_commit();
        }

        const float* wbuf = bufs[wnd & 1];
        const float* sk = sbase + wnd * 72;
        #pragma unroll 3
        for (int kr = 0; kr < 9; ++kr) {
            const float* wrow = wbuf + (kg * 9 + kr) * 64;
            const ulonglong2 wLo = *(const ulonglong2*)(wrow + cg * 4);      // cols 4cg..+3
            const ulonglong2 wHi = *(const ulonglong2*)(wrow + 32 + cg * 4); // cols 32+4cg..+3
            #pragma unroll
            for (int i = 0; i < 8; ++i) {
                const float sv = sk[i * SST + kr];
                const unsigned long long ss = pack2(sv, sv);
                fma2(acc[i][0], ss, wLo.x);
                fma2(acc[i][1], ss, wLo.y);
                fma2(acc[i][2], ss, wHi.x);
                fma2(acc[i][3], ss, wHi.y);
            }
        }
    }
    __syncthreads();   // all s_sm reads done; safe to reuse for partials

    // ---- stash 64 partial floats per thread in s_sm (stride 68) ----
    {
        float* pb = s_sm + tid * 68;
        #pragma unroll
        for (int i = 0; i < 8; ++i) {
            ulonglong2 t0; t0.x = acc[i][0]; t0.y = acc[i][1];
            ulonglong2 t1; t1.x = acc[i][2]; t1.y = acc[i][3];
            *(ulonglong2*)(pb + i * 8)     = t0;
            *(ulonglong2*)(pb + i * 8 + 4) = t1;
        }
    }
    __syncthreads();

    // ---- reduce 8 K-groups; thread -> (row r, cols {4cs..+3, 32+4cs..+3}) ----
    {
        const int r  = tid >> 3;
        const int cs = tid & 7;
        const int rgp = r >> 3, ii = r & 7;
        unsigned long long p0 = 0, p1 = 0, p2 = 0, p3 = 0;
        #pragma unroll
        for (int g = 0; g < 8; ++g) {
            const float* pb = s_sm + (g * 32 + rgp * 8 + cs) * 68 + ii * 8;
            const ulonglong2 a = *(const ulonglong2*)(pb);
            const ulonglong2 b = *(const ulonglong2*)(pb + 4);
            add2(p0, a.x); add2(p1, a.y); add2(p2, b.x); add2(p3, b.y);
        }
        const float4 bv_0 = *(const float4*)(bias + cs * 4);
        const float4 bv_1 = *(const float4*)(bias + 32 + cs * 4);
        const float2 f0 = unpack2(p0), f1 = unpack2(p1);
        const float2 f2 = unpack2(p2), f3 = unpack2(p3);
        float* op = out + (size_t)(bv0 + r) * OO;
        *(float4*)(op + cs * 4)      = make_float4(f0.x + bv_0.x, f0.y + bv_0.y,
                                                   f1.x + bv_0.z, f1.y + bv_0.w);
        *(float4*)(op + 32 + cs * 4) = make_float4(f2.x + bv_1.x, f2.y + bv_1.y,
                                                   f3.x + bv_1.z, f3.y + bv_1.w);
    }
}

// ---------------------------------------------------------------------------
// Host launcher (graph-capturable: kernel launches only)
// ---------------------------------------------------------------------------
extern "C" void kernel_launch(void* const* d_in, const int* in_sizes, int n_in,
                              void* d_out, int out_size) {
    const float* x   = (const float*)d_in[0];  // [B,N,C]
    const int*   adj = (const int*)  d_in[1];  // [B,N,K]
    const float* W   = (const float*)d_in[2];  // [M,O,C]
    const float* b   = (const float*)d_in[3];  // [O]
    const float* u   = (const float*)d_in[4];  // [M,C]
    const float* v   = (const float*)d_in[5];  // [M,C]
    const float* c   = (const float*)d_in[6];  // [M]
    float* out = (float*)d_out;

    feast_prep<<<UVX_BLOCKS + (MM * OO * CC + 255) / 256, 256>>>(x, u, v, c, W);

    const size_t smem_bytes =
        (size_t)(S_FLOATS + 2 * WT_FLOATS) * sizeof(float);  // 110720 B
    cudaFuncSetAttribute(feast_main, cudaFuncAttributeMaxDynamicSharedMemorySize,
                         (int)smem_bytes);
    feast_main<<<NVT / VTILE, NTHREADS, smem_bytes>>>(x, adj, b, out);
}